// round 15
// baseline (speedup 1.0000x reference)
#include <cuda_runtime.h>
#include <cuda_bf16.h>
#include <math.h>
#include <stdint.h>

// ---------------- problem constants ----------------
#define Bsz   131072
#define Dd    256
#define Lc    8
#define NCc   10
#define BN_EPS 1e-5f
#define DGCONST -235.24826450039622f   // D * GCONST

#define MROW  32
#define NTHR  256
#define NBLK  (Bsz/MROW)      // 4096 CTAs

// smem: XHI 16K | XLO 16K | HB 16K | BW 2x32K  = 112KB/CTA, 2 CTAs/SM
#define XHIo 0
#define XLOo 16384
#define HBo  32768
#define BWo  49152
#define SMEMSZ 114688

// ---------------- static device scratch ----------------
__device__ float g_bufA[(size_t)Bsz*Dd];          // h
__device__ float g_scale[Lc*Dd];
__device__ float g_sumlog[Lc];
__device__ float g_po[Lc*Dd];
__device__ float g_part[(size_t)NBLK*2*Dd];
__device__ float g_stats[2*Dd];
// pre-swizzled bf16 weight images (chunked K=64 smem layout; chunk = 32KB = 16384 elems)
__device__ __nv_bfloat16 g_w1t[(size_t)Lc*32768];
__device__ __nv_bfloat16 g_w2t[(size_t)Lc*65536];   // column-PERMUTED
__device__ __nv_bfloat16 g_ph [(size_t)Lc*65536];   // P' = P*diag(scale), hi
__device__ __nv_bfloat16 g_pl [(size_t)Lc*65536];
__device__ __nv_bfloat16 g_whh[65536];
__device__ __nv_bfloat16 g_whl[65536];

// ---------------- helpers ----------------
__device__ __forceinline__ uint32_t packbf2(float a, float b) {
    __nv_bfloat162 t = __floats2bfloat162_rn(a, b);
    return *(uint32_t*)&t;
}
__device__ __forceinline__ float2 unpackbf2(uint32_t w) {
    __nv_bfloat162 t = *(__nv_bfloat162*)&w;
    return __bfloat1622float2(t);
}
__device__ __forceinline__ void split2t(float a, float b, uint32_t& hw, uint32_t& lw) {
    uint32_t ia = __float_as_uint(a), ib = __float_as_uint(b);
    asm("prmt.b32 %0, %1, %2, 0x7632;" : "=r"(hw) : "r"(ia), "r"(ib));
    float ha = __uint_as_float(ia & 0xFFFF0000u);
    float hb = __uint_as_float(ib & 0xFFFF0000u);
    uint32_t il = __float_as_uint(a - ha), jl = __float_as_uint(b - hb);
    asm("prmt.b32 %0, %1, %2, 0x7632;" : "=r"(lw) : "r"(il), "r"(jl));
}
__device__ __forceinline__ float fast_tanh_scaled(float a) {
    float e = __expf(-0.2f * a);
    return 1.9f * __fdividef(1.f - e, 1.f + e);
}
__device__ __forceinline__ void cpab(void* dst_smem, const void* src) {
    unsigned s = (unsigned)__cvta_generic_to_shared(dst_smem);
    asm volatile("cp.async.cg.shared.global [%0], [%1], 16;" :: "r"(s), "l"(src));
}
#define CP_COMMIT asm volatile("cp.async.commit_group;")
#define CP_WAIT0  asm volatile("cp.async.wait_group 0;")

#define MMA(cd, a0, a1, a2, a3, b0, b1) \
    asm volatile("mma.sync.aligned.m16n8k16.row.col.f32.bf16.bf16.f32 " \
        "{%0,%1,%2,%3}, {%4,%5,%6,%7}, {%8,%9}, {%0,%1,%2,%3};" \
        : "+f"((cd)[0]), "+f"((cd)[1]), "+f"((cd)[2]), "+f"((cd)[3]) \
        : "r"(a0), "r"(a1), "r"(a2), "r"(a3), "r"(b0), "r"(b1))

#define LDSM4(r0, r1, r2, r3, addr) \
    asm volatile("ldmatrix.sync.aligned.m8n8.x4.shared.b16 {%0,%1,%2,%3}, [%4];" \
        : "=r"(r0), "=r"(r1), "=r"(r2), "=r"(r3) : "r"(addr))

// stage one 32KB chunk with 256 threads
__device__ __forceinline__ void stage32(char* dst, const __nv_bfloat16* src, int tid) {
    const char* s = (const char*)src;
    #pragma unroll
    for (int i = 0; i < 8; i++) cpab(dst + tid*16 + i*4096, s + tid*16 + i*4096);
}
__device__ __forceinline__ int imgoff(int n, int k) {
    return n*64 + (((k >> 3) ^ (n & 7)) << 3) + (k & 7);
}

// ---------------- preprocessing (3 launches, coalesced) ----------------
__global__ void prep_scale(const float* __restrict__ gs) {
    __shared__ float red[256];
    int l = blockIdx.x, d = threadIdx.x;
    float x  = 0.5f * gs[l*Dd + d];
    float sp = (x > 20.f) ? x : log1pf(expf(x));
    float s  = 0.2f * sp;
    g_scale[l*Dd + d] = s;
    red[d] = logf(s);
    __syncthreads();
    #pragma unroll
    for (int o = 128; o; o >>= 1) { if (d < o) red[d] += red[d + o]; __syncthreads(); }
    if (d == 0) g_sumlog[l] = red[0];
}
#define W1T_CNT (Lc*256*16)
#define W2T_CNT (Lc*256*32)
#define WHT_CNT (256*32)
__global__ void prep_wimg(const float* __restrict__ W1, const float* __restrict__ W2,
                          const float* __restrict__ Wh1) {
    int idx = blockIdx.x * 256 + threadIdx.x;
    if (idx < W1T_CNT) {
        int n = idx & 255, ko = ((idx >> 8) & 15) * 8, l = idx >> 12;
        __nv_bfloat16 v[8];
        #pragma unroll
        for (int j = 0; j < 8; j++)
            v[j] = __float2bfloat16(W1[((size_t)l*128 + ko + j)*256 + n]);
        *(uint4*)&g_w1t[(size_t)l*32768 + (ko>>6)*16384 + imgoff(n, ko & 63)] = *(uint4*)v;
    } else if (idx < W1T_CNT + W2T_CNT) {
        int j2 = idx - W1T_CNT;
        int n = j2 & 255, ko = ((j2 >> 8) & 31) * 8, l = j2 >> 13;
        int jr = ((n & 127) >> 4) * 32 + ((n >> 7) << 4) + (n & 15);
        __nv_bfloat16 v[8];
        #pragma unroll
        for (int j = 0; j < 8; j++)
            v[j] = __float2bfloat16(W2[((size_t)l*256 + ko + j)*256 + n]);
        *(uint4*)&g_w2t[(size_t)l*65536 + (ko>>6)*16384 + imgoff(jr, ko & 63)] = *(uint4*)v;
    } else if (idx < W1T_CNT + W2T_CNT + WHT_CNT) {
        int j2 = idx - (W1T_CNT + W2T_CNT);
        int n = j2 & 255, ko = (j2 >> 8) * 8;
        __nv_bfloat16 vh[8], vl[8];
        #pragma unroll
        for (int j = 0; j < 8; j++) {
            float v = Wh1[((size_t)(ko + j))*256 + n];
            vh[j] = __float2bfloat16(v);
            vl[j] = __float2bfloat16(v - __bfloat162float(vh[j]));
        }
        size_t o = (size_t)(ko>>6)*16384 + imgoff(n, ko & 63);
        *(uint4*)&g_whh[o] = *(uint4*)vh;
        *(uint4*)&g_whl[o] = *(uint4*)vl;
    }
}
#define PT_CNT (Lc*256*32)
__global__ void prep_pimg(const float* __restrict__ P, const float* __restrict__ go) {
    int idx = blockIdx.x * 256 + threadIdx.x;
    if (idx < PT_CNT) {
        int ko = (idx & 31) * 8, n = (idx >> 5) & 255, l = idx >> 13;
        __nv_bfloat16 vh[8], vl[8];
        #pragma unroll
        for (int j = 0; j < 8; j++) {
            float v = P[((size_t)l*256 + n)*256 + ko + j] * g_scale[l*Dd + ko + j];
            vh[j] = __float2bfloat16(v);
            vl[j] = __float2bfloat16(v - __bfloat162float(vh[j]));
        }
        size_t o = (size_t)l*65536 + (ko>>6)*16384 + imgoff(n, ko & 63);
        *(uint4*)&g_ph[o] = *(uint4*)vh;
        *(uint4*)&g_pl[o] = *(uint4*)vl;
    } else if (idx < PT_CNT + Lc*256) {
        int j = idx - PT_CNT;
        int l = j >> 8, n = j & 255;
        const float* pr = P + ((size_t)l*256 + n)*256;
        const float* o  = go + l*Dd;
        float acc = 0.f;
        for (int k = 0; k < 256; k++) acc += o[k] * pr[k];
        g_po[l*Dd + n] = acc;
    }
}

// single-term pass: cacc += A(achunk) @ B  (A rows 0..31 from AbaseU image)
#define PASS_1T(AbaseU, achunk, BbufU) do {                                          \
    _Pragma("unroll")                                                                \
    for (int ks = 0; ks < 64; ks += 16) {                                            \
        int gA = ((achunk) << 3) + (ks >> 3) + laneHi;                               \
        uint32_t A_[2][4], B_[2][4];                                                 \
        _Pragma("unroll")                                                            \
        for (int mt = 0; mt < 2; mt++)                                               \
            LDSM4(A_[mt][0], A_[mt][1], A_[mt][2], A_[mt][3],                        \
                  (AbaseU) + (uint32_t)(mt*16*512 + aRowB + ((gA ^ key) << 4)));     \
        uint32_t bsw_ = (uint32_t)(((((ks >> 3) + bsel) ^ key) << 4));               \
        LDSM4(B_[0][0], B_[0][1], B_[0][2], B_[0][3], (BbufU) + (uint32_t)bRow0 + bsw_); \
        LDSM4(B_[1][0], B_[1][1], B_[1][2], B_[1][3], (BbufU) + (uint32_t)bRow1 + bsw_); \
        _Pragma("unroll")                                                            \
        for (int p = 0; p < 2; p++)                                                  \
            _Pragma("unroll")                                                        \
            for (int q = 0; q < 2; q++) {                                            \
                int nt = p*2 + q;                                                    \
                MMA(cacc[0][nt], A_[0][0], A_[0][1], A_[0][2], A_[0][3], B_[p][q*2], B_[p][q*2+1]); \
                MMA(cacc[1][nt], A_[1][0], A_[1][1], A_[1][2], A_[1][3], B_[p][q*2], B_[p][q*2+1]); \
            }                                                                        \
    }                                                                                \
} while (0)

// two-term pass: cacc += Ah(achunk)@B + Al(achunk)@B
#define PASS_2T(achunk, BbufU) do {                                                  \
    _Pragma("unroll")                                                                \
    for (int ks = 0; ks < 64; ks += 16) {                                            \
        int gA = ((achunk) << 3) + (ks >> 3) + laneHi;                               \
        uint32_t Ah_[2][4], Al_[2][4], B_[2][4];                                     \
        _Pragma("unroll")                                                            \
        for (int mt = 0; mt < 2; mt++) {                                             \
            uint32_t ab_ = (uint32_t)(mt*16*512 + aRowB + ((gA ^ key) << 4));        \
            LDSM4(Ah_[mt][0], Ah_[mt][1], Ah_[mt][2], Ah_[mt][3], XHI + ab_);        \
            LDSM4(Al_[mt][0], Al_[mt][1], Al_[mt][2], Al_[mt][3], XLO + ab_);        \
        }                                                                            \
        uint32_t bsw_ = (uint32_t)(((((ks >> 3) + bsel) ^ key) << 4));               \
        LDSM4(B_[0][0], B_[0][1], B_[0][2], B_[0][3], (BbufU) + (uint32_t)bRow0 + bsw_); \
        LDSM4(B_[1][0], B_[1][1], B_[1][2], B_[1][3], (BbufU) + (uint32_t)bRow1 + bsw_); \
        _Pragma("unroll")                                                            \
        for (int p = 0; p < 2; p++)                                                  \
            _Pragma("unroll")                                                        \
            for (int q = 0; q < 2; q++) {                                            \
                int nt = p*2 + q;                                                    \
                _Pragma("unroll")                                                    \
                for (int mt = 0; mt < 2; mt++) {                                     \
                    MMA(cacc[mt][nt], Ah_[mt][0], Ah_[mt][1], Ah_[mt][2], Ah_[mt][3], B_[p][q*2], B_[p][q*2+1]); \
                    MMA(cacc[mt][nt], Al_[mt][0], Al_[mt][1], Al_[mt][2], Al_[mt][3], B_[p][q*2], B_[p][q*2+1]); \
                }                                                                    \
            }                                                                        \
    }                                                                                \
} while (0)

// wait previous chunk, fence, stage next chunk into the other buffer
#define PIPE_STAGE(srcptr) do {                                                      \
    CP_WAIT0; __syncthreads();                                                       \
    stage32(bw + (cb ^ 32768u), (srcptr), tid); CP_COMMIT;                           \
} while (0)

#define INIT_ACC_G(bias) do {                                                        \
    _Pragma("unroll")                                                                \
    for (int nt = 0; nt < 4; nt++) {                                                 \
        int c_ = c_base + nt*8;                                                      \
        float f0_ = __ldg((bias) + c_), f1_ = __ldg((bias) + c_ + 1);                \
        _Pragma("unroll")                                                            \
        for (int mt = 0; mt < 2; mt++) {                                             \
            cacc[mt][nt][0] = f0_; cacc[mt][nt][1] = f1_;                            \
            cacc[mt][nt][2] = f0_; cacc[mt][nt][3] = f1_;                            \
        }                                                                            \
    }                                                                                \
} while (0)

// ---------------- mega-fused: flow(8 layers) + log_px + head GEMM ----------------
__global__ void __launch_bounds__(NTHR, 2) flow_fused(
    const float* __restrict__ xin, float* __restrict__ hout,
    const float* __restrict__ b1, const float* __restrict__ b2,
    const float* __restrict__ bh1, float* __restrict__ logpx)
{
    extern __shared__ char smem[];
    const uint32_t su = (uint32_t)__cvta_generic_to_shared(smem);
    const uint32_t XHI = su + XHIo, XLO = su + XLOo, HBu = su + HBo, BWu = su + BWo;
    char* bw = smem + BWo;
    float* HBf = (float*)(smem + HBo);

    const int tid = threadIdx.x, lane = tid & 31;
    const int warpN = tid >> 5;                  // 0..7
    const int g = lane >> 2, t = lane & 3;
    const int n0 = warpN * 32;
    const int laneHi = lane >> 4;
    const int key = lane & 7;
    const int aRowB = (lane & 15) * 512;
    const int nloc = ((lane >> 4) << 3) + (lane & 7);
    const int bRow0 = (n0 + nloc) * 128, bRow1 = (n0 + 16 + nloc) * 128;
    const int bsel = (lane >> 3) & 1;
    const int c_base = n0 + 2*t;

    uint32_t cb = 0;
    // prologue: stage layer-0 W1 chunk0 -> buf0
    stage32(bw, g_w1t, tid); CP_COMMIT;

    // load + split input x once
    {
        const float4* src = (const float4*)(xin + (size_t)blockIdx.x * MROW * Dd);
        #pragma unroll
        for (int i = tid; i < MROW * Dd / 4; i += NTHR) {
            int r = i >> 6, c = (i & 63) * 4;
            float4 v = src[i];
            uint32_t h0, l0, h1, l1;
            split2t(v.x, v.y, h0, l0);
            split2t(v.z, v.w, h1, l1);
            int off = r*512 + (((c >> 3) ^ (r & 7)) << 4) + (c & 7)*2;
            *(uint2*)(smem + XHIo + off) = make_uint2(h0, h1);
            *(uint2*)(smem + XLOo + off) = make_uint2(l0, l1);
        }
    }

    float cacc[2][4][4];
    float ldacc = 0.f;

    #pragma unroll 1
    for (int layer = 0; layer < Lc; layer++) {
        const float* bb2 = b2 + layer*Dd;
        const __nv_bfloat16* w1img = g_w1t + (size_t)layer*32768;
        const __nv_bfloat16* w2img = g_w2t + (size_t)layer*65536;
        const __nv_bfloat16* phimg = g_ph  + (size_t)layer*65536;
        const __nv_bfloat16* plimg = g_pl  + (size_t)layer*65536;
        const __nv_bfloat16* nxt0 = (layer + 1 < Lc) ? g_w1t + (size_t)(layer+1)*32768 : g_whh;

        // ===== GEMM1 (2 chunks) =====
        INIT_ACC_G(b1 + layer*Dd);
        PIPE_STAGE(w1img + 16384);                 // stage W1c1
        PASS_1T(XHI, 0, BWu + cb); cb ^= 32768u;
        PIPE_STAGE(w2img);                         // stage W2c0
        PASS_1T(XHI, 1, BWu + cb); cb ^= 32768u;
        // relu -> HB
        #pragma unroll
        for (int nt = 0; nt < 4; nt++) {
            int c = c_base + nt*8;
            int csw = ((c >> 3) ^ g) << 4;
            #pragma unroll
            for (int mt = 0; mt < 2; mt++) {
                int r = mt*16 + g;
                float* cf = cacc[mt][nt];
                *(uint32_t*)(smem + HBo + r*512     + csw + 4*t) =
                    packbf2(fmaxf(cf[0], 0.f), fmaxf(cf[1], 0.f));
                *(uint32_t*)(smem + HBo + (r+8)*512 + csw + 4*t) =
                    packbf2(fmaxf(cf[2], 0.f), fmaxf(cf[3], 0.f));
            }
        }

        // ===== GEMM2 (4 chunks, output cols permuted) =====
        #pragma unroll
        for (int nt = 0; nt < 4; nt++) {
            int p = nt >> 1, q = nt & 1;
            int c2 = p*128 + warpN*16 + q*8 + 2*t;
            float f0 = __ldg(bb2 + c2), f1 = __ldg(bb2 + c2 + 1);
            #pragma unroll
            for (int mt = 0; mt < 2; mt++) {
                cacc[mt][nt][0] = f0; cacc[mt][nt][1] = f1;
                cacc[mt][nt][2] = f0; cacc[mt][nt][3] = f1;
            }
        }
        #pragma unroll
        for (int c2 = 0; c2 < 4; c2++) {
            PIPE_STAGE((c2 < 3) ? (w2img + (c2+1)*16384) : phimg);
            PASS_1T(HBu, c2, BWu + cb); cb ^= 32768u;
        }

        // ===== coupling epilogue (register-local; overlaps Phc0 load & other warps) =====
        float lds0, lds1, lds2, lds3;
        {
            float lds[2][2] = {{0.f, 0.f}, {0.f, 0.f}};
            #pragma unroll
            for (int q = 0; q < 2; q++) {
                int cx = 128 + warpN*16 + q*8 + 2*t;
                #pragma unroll
                for (int mt = 0; mt < 2; mt++) {
                    #pragma unroll
                    for (int half = 0; half < 2; half++) {
                        int i0 = half*2, r = mt*16 + g + half*8;
                        float s0 = fast_tanh_scaled(cacc[mt][q][i0]);
                        float s1 = fast_tanh_scaled(cacc[mt][q][i0 + 1]);
                        lds[mt][half] += s0 + s1;
                        float a20 = 0.1f * cacc[mt][2 + q][i0];
                        float a21 = 0.1f * cacc[mt][2 + q][i0 + 1];
                        int xo = r*512 + (((cx >> 3) ^ g) << 4) + 4*t;
                        float2 hv = unpackbf2(*(uint32_t*)(smem + XHIo + xo));
                        float2 lv = unpackbf2(*(uint32_t*)(smem + XLOo + xo));
                        float v0 = (hv.x + lv.x) * __expf(s0) + a20;
                        float v1 = (hv.y + lv.y) * __expf(s1) + a21;
                        uint32_t hw, lw; split2t(v0, v1, hw, lw);
                        *(uint32_t*)(smem + XHIo + xo) = hw;
                        *(uint32_t*)(smem + XLOo + xo) = lw;
                    }
                }
            }
            #pragma unroll
            for (int mt = 0; mt < 2; mt++)
                #pragma unroll
                for (int half = 0; half < 2; half++) {
                    float v = lds[mt][half];
                    v += __shfl_xor_sync(0xffffffffu, v, 1);
                    v += __shfl_xor_sync(0xffffffffu, v, 2);
                    lds[mt][half] = v;
                }
            lds0 = lds[0][0]; lds1 = lds[0][1]; lds2 = lds[1][0]; lds3 = lds[1][1];
        }

        // ===== GEMM3 (4 chunks x {hi 2-term, lo 1-term} passes) =====
        INIT_ACC_G(g_po + layer*Dd);
        #pragma unroll
        for (int c3 = 0; c3 < 4; c3++) {
            PIPE_STAGE(plimg + c3*16384);          // stage Pl c3 (sync also fences G2 HB reads)
            if (c3 == 0 && t == 0) {               // logdet partials (HB free now)
                HBf[(g)*8 + warpN]      = lds0;
                HBf[(g + 8)*8 + warpN]  = lds1;
                HBf[(16 + g)*8 + warpN] = lds2;
                HBf[(24 + g)*8 + warpN] = lds3;
            }
            PASS_2T(c3, BWu + cb); cb ^= 32768u;   // Ah,Al x Ph
            PIPE_STAGE((c3 < 3) ? (phimg + (c3+1)*16384) : nxt0);
            PASS_1T(XHI, c3, BWu + cb); cb ^= 32768u;   // Ah x Pl
        }
        __syncthreads();                           // S_end: all X/HBf reads & writes fenced

        // logdet
        if (tid < MROW) {
            float rs = 0.f;
            #pragma unroll
            for (int w = 0; w < 8; w++) rs += HBf[tid*8 + w];
            ldacc += rs + g_sumlog[layer];
        }
        // split accumulators back into XHI/XLO (final layer = z)
        #pragma unroll
        for (int nt = 0; nt < 4; nt++) {
            int c = c_base + nt*8;
            int csw = ((c >> 3) ^ g) << 4;
            #pragma unroll
            for (int mt = 0; mt < 2; mt++) {
                float* cf = cacc[mt][nt];
                #pragma unroll
                for (int half = 0; half < 2; half++) {
                    int r = mt*16 + g + half*8;
                    uint32_t hw, lw;
                    split2t(cf[half*2 + 0], cf[half*2 + 1], hw, lw);
                    *(uint32_t*)(smem + XHIo + r*512 + csw + 4*t) = hw;
                    *(uint32_t*)(smem + XLOo + r*512 + csw + 4*t) = lw;
                }
            }
        }
    }

    // ===================== fused tail: log_px =====================
    {
        float z2[2][2];
        #pragma unroll
        for (int mt = 0; mt < 2; mt++)
            #pragma unroll
            for (int half = 0; half < 2; half++) {
                float s = 0.f;
                #pragma unroll
                for (int nt = 0; nt < 4; nt++) {
                    float a = cacc[mt][nt][half*2 + 0], b = cacc[mt][nt][half*2 + 1];
                    s += a*a + b*b;
                }
                s += __shfl_xor_sync(0xffffffffu, s, 1);
                s += __shfl_xor_sync(0xffffffffu, s, 2);
                z2[mt][half] = s;
            }
        __syncthreads();               // S10: layer-7 logdet reads done
        if (t == 0) {
            #pragma unroll
            for (int mt = 0; mt < 2; mt++)
                #pragma unroll
                for (int half = 0; half < 2; half++) {
                    int r = mt*16 + g + half*8;
                    HBf[r*8 + warpN] = z2[mt][half];
                }
        }
        __syncthreads();               // S11
        if (tid < MROW) {
            float ss = 0.f;
            #pragma unroll
            for (int w = 0; w < 8; w++) ss += HBf[tid*8 + w];
            logpx[(size_t)blockIdx.x * MROW + tid] =
                (DGCONST - 0.5f*ss + ldacc) * (1.0f/Dd);
        }
    }

    // ===================== head GEMM: h = z @ Wh1 (3-term) + bh1 =====================
    {
        INIT_ACC_G(bh1);
        #pragma unroll
        for (int c = 0; c < 4; c++) {
            PIPE_STAGE(g_whl + c*16384);
            PASS_2T(c, BWu + cb); cb ^= 32768u;
            CP_WAIT0; __syncthreads();
            if (c < 3) { stage32(bw + (cb ^ 32768u), g_whh + (c+1)*16384, tid); CP_COMMIT; }
            PASS_1T(XHI, c, BWu + cb); cb ^= 32768u;
        }
        __syncthreads();               // S12: z reads done, smem free

        float* stg = (float*)smem;     // [32][264] fp32 overlay
        #pragma unroll
        for (int mt = 0; mt < 2; mt++)
            #pragma unroll
            for (int half = 0; half < 2; half++) {
                int rl = mt*16 + g + half*8;
                int r  = blockIdx.x * MROW + rl;
                #pragma unroll
                for (int nt = 0; nt < 4; nt++) {
                    int c = c_base + nt*8;
                    float* cf = cacc[mt][nt];
                    float v0 = cf[half*2 + 0];
                    float v1 = cf[half*2 + 1];
                    *(float2*)(hout + (size_t)r*Dd + c) = make_float2(v0, v1);
                    stg[(size_t)rl*264 + c]     = v0;
                    stg[(size_t)rl*264 + c + 1] = v1;
                }
            }
        __syncthreads();               // S13
        if (tid < Dd) {
            float s = 0.f, q = 0.f;
            #pragma unroll 4
            for (int r = 0; r < MROW; r++) {
                float v = stg[(size_t)r*264 + tid];
                s += v; q += v * v;
            }
            g_part[(size_t)blockIdx.x*2*Dd + tid]      = s;
            g_part[(size_t)blockIdx.x*2*Dd + Dd + tid] = q;
        }
    }
}

// ---------------- BN stats fold ----------------
__global__ void stats_kernel(const float* __restrict__ gamma, const float* __restrict__ beta) {
    int c = threadIdx.x;
    float s0=0.f,s1=0.f,s2=0.f,s3=0.f, q0=0.f,q1=0.f,q2=0.f,q3=0.f;
    for (int i = 0; i < NBLK; i += 4) {
        s0 += g_part[(size_t)(i+0)*2*Dd + c];   q0 += g_part[(size_t)(i+0)*2*Dd + Dd + c];
        s1 += g_part[(size_t)(i+1)*2*Dd + c];   q1 += g_part[(size_t)(i+1)*2*Dd + Dd + c];
        s2 += g_part[(size_t)(i+2)*2*Dd + c];   q2 += g_part[(size_t)(i+2)*2*Dd + Dd + c];
        s3 += g_part[(size_t)(i+3)*2*Dd + c];   q3 += g_part[(size_t)(i+3)*2*Dd + Dd + c];
    }
    float s = (s0+s1)+(s2+s3), q = (q0+q1)+(q2+q3);
    float mu  = s * (1.f/Bsz);
    float var = q * (1.f/Bsz) - mu*mu;
    float a = gamma[c] * rsqrtf(var + BN_EPS);
    g_stats[c]      = a;
    g_stats[Dd + c] = beta[c] - mu * a;
}

// ---------------- logits ----------------
__global__ void __launch_bounds__(256) logits_kernel(
    const float* __restrict__ h, const float* __restrict__ Wh2,
    const float* __restrict__ bh2, float* __restrict__ out)
{
    __shared__ float w2s[Dd*NCc];
    __shared__ float As[Dd], Bs[Dd];
    int tid = threadIdx.x;
    for (int i = tid; i < Dd*NCc; i += 256) w2s[i] = Wh2[i];
    if (tid < Dd) { As[tid] = g_stats[tid]; Bs[tid] = g_stats[Dd + tid]; }
    __syncthreads();

    int warp = tid >> 5, lane = tid & 31;
    size_t row = (size_t)blockIdx.x * 8 + warp;
    const float4* hr = (const float4*)(h + row*Dd);
    float4 v0 = hr[lane*2], v1 = hr[lane*2 + 1];
    int k0 = lane * 8;
    float hn[8];
    hn[0] = fmaxf(v0.x*As[k0+0] + Bs[k0+0], 0.f);
    hn[1] = fmaxf(v0.y*As[k0+1] + Bs[k0+1], 0.f);
    hn[2] = fmaxf(v0.z*As[k0+2] + Bs[k0+2], 0.f);
    hn[3] = fmaxf(v0.w*As[k0+3] + Bs[k0+3], 0.f);
    hn[4] = fmaxf(v1.x*As[k0+4] + Bs[k0+4], 0.f);
    hn[5] = fmaxf(v1.y*As[k0+5] + Bs[k0+5], 0.f);
    hn[6] = fmaxf(v1.z*As[k0+6] + Bs[k0+6], 0.f);
    hn[7] = fmaxf(v1.w*As[k0+7] + Bs[k0+7], 0.f);

    float acc[NCc];
    #pragma unroll
    for (int c = 0; c < NCc; c++) acc[c] = 0.f;
    #pragma unroll
    for (int kk = 0; kk < 8; kk++) {
        float x = hn[kk];
        const float* wr = &w2s[(k0+kk)*NCc];
        #pragma unroll
        for (int c = 0; c < NCc; c++) acc[c] += x * wr[c];
    }
    #pragma unroll
    for (int c = 0; c < NCc; c++) {
        #pragma unroll
        for (int o = 16; o; o >>= 1) acc[c] += __shfl_down_sync(0xffffffffu, acc[c], o);
    }
    if (lane == 0) {
        #pragma unroll
        for (int c = 0; c < NCc; c++) out[row*NCc + c] = acc[c] + __ldg(bh2 + c);
    }
}

// ---------------- launch ----------------
extern "C" void kernel_launch(void* const* d_in, const int* in_sizes, int n_in,
                              void* d_out, int out_size)
{
    const float* feat  = (const float*)d_in[0];
    const float* W1    = (const float*)d_in[1];
    const float* b1    = (const float*)d_in[2];
    const float* W2    = (const float*)d_in[3];
    const float* b2    = (const float*)d_in[4];
    const float* gs    = (const float*)d_in[5];
    const float* go    = (const float*)d_in[6];
    const float* P     = (const float*)d_in[7];
    const float* Wh1   = (const float*)d_in[8];
    const float* bh1   = (const float*)d_in[9];
    const float* gamma = (const float*)d_in[10];
    const float* beta  = (const float*)d_in[11];
    const float* Wh2   = (const float*)d_in[12];
    const float* bh2   = (const float*)d_in[13];
    float* out = (float*)d_out;

    cudaFuncSetAttribute(flow_fused, cudaFuncAttributeMaxDynamicSharedMemorySize, SMEMSZ);

    float* bufA = nullptr;
    cudaGetSymbolAddress((void**)&bufA, g_bufA);

    prep_scale<<<Lc, 256>>>(gs);
    prep_wimg<<<(W1T_CNT + W2T_CNT + WHT_CNT + 255)/256, 256>>>(W1, W2, Wh1);
    prep_pimg<<<(PT_CNT + Lc*256 + 255)/256, 256>>>(P, go);

    flow_fused<<<NBLK, NTHR, SMEMSZ>>>(feat, bufA, b1, b2, bh1, out);

    stats_kernel<<<1, 256>>>(gamma, beta);
    logits_kernel<<<Bsz/8, 256>>>(bufA, Wh2, bh2, out + Bsz);
}

// round 16
// speedup vs baseline: 1.1645x; 1.1645x over previous
#include <cuda_runtime.h>
#include <cuda_bf16.h>
#include <math.h>
#include <stdint.h>

// ---------------- problem constants ----------------
#define Bsz   131072
#define Dd    256
#define Lc    8
#define NCc   10
#define BN_EPS 1e-5f
#define DGCONST -235.24826450039622f   // D * GCONST

#define MROW  32
#define NTHR  256
#define NBLK  (Bsz/MROW)      // 4096 CTAs

// smem: XHI 16K | XLO 16K | HB 16K | BW 2x32K  = 112KB/CTA, 2 CTAs/SM
#define XHIo 0
#define XLOo 16384
#define HBo  32768
#define BWo  49152
#define SMEMSZ 114688

// ---------------- static device scratch ----------------
__device__ float g_bufA[(size_t)Bsz*Dd];          // h
__device__ float g_scale[Lc*Dd];
__device__ float g_sumlog[Lc];
__device__ float g_po[Lc*Dd];
__device__ float g_part[(size_t)NBLK*2*Dd];
__device__ float g_part2[64*2*Dd];
__device__ float g_stats[2*Dd];
// pre-swizzled bf16 weight images (chunked K=64 smem layout; chunk = 32KB = 16384 elems)
__device__ __nv_bfloat16 g_w1t[(size_t)Lc*32768];
__device__ __nv_bfloat16 g_w2t[(size_t)Lc*65536];   // column-PERMUTED
__device__ __nv_bfloat16 g_ph [(size_t)Lc*65536];   // P' = P*diag(scale), hi
__device__ __nv_bfloat16 g_pl [(size_t)Lc*65536];
__device__ __nv_bfloat16 g_whh[65536];
__device__ __nv_bfloat16 g_whl[65536];

// ---------------- helpers ----------------
__device__ __forceinline__ uint32_t packbf2(float a, float b) {
    __nv_bfloat162 t = __floats2bfloat162_rn(a, b);
    return *(uint32_t*)&t;
}
__device__ __forceinline__ float2 unpackbf2(uint32_t w) {
    __nv_bfloat162 t = *(__nv_bfloat162*)&w;
    return __bfloat1622float2(t);
}
__device__ __forceinline__ void split2t(float a, float b, uint32_t& hw, uint32_t& lw) {
    uint32_t ia = __float_as_uint(a), ib = __float_as_uint(b);
    asm("prmt.b32 %0, %1, %2, 0x7632;" : "=r"(hw) : "r"(ia), "r"(ib));
    float ha = __uint_as_float(ia & 0xFFFF0000u);
    float hb = __uint_as_float(ib & 0xFFFF0000u);
    uint32_t il = __float_as_uint(a - ha), jl = __float_as_uint(b - hb);
    asm("prmt.b32 %0, %1, %2, 0x7632;" : "=r"(lw) : "r"(il), "r"(jl));
}
__device__ __forceinline__ float fast_tanh_scaled(float a) {
    float e = __expf(-0.2f * a);
    return 1.9f * __fdividef(1.f - e, 1.f + e);
}
__device__ __forceinline__ void cpab(void* dst_smem, const void* src) {
    unsigned s = (unsigned)__cvta_generic_to_shared(dst_smem);
    asm volatile("cp.async.cg.shared.global [%0], [%1], 16;" :: "r"(s), "l"(src));
}
#define CP_COMMIT asm volatile("cp.async.commit_group;")
#define CP_WAIT0  asm volatile("cp.async.wait_group 0;")

#define MMA(cd, a0, a1, a2, a3, b0, b1) \
    asm volatile("mma.sync.aligned.m16n8k16.row.col.f32.bf16.bf16.f32 " \
        "{%0,%1,%2,%3}, {%4,%5,%6,%7}, {%8,%9}, {%0,%1,%2,%3};" \
        : "+f"((cd)[0]), "+f"((cd)[1]), "+f"((cd)[2]), "+f"((cd)[3]) \
        : "r"(a0), "r"(a1), "r"(a2), "r"(a3), "r"(b0), "r"(b1))

#define LDSM4(r0, r1, r2, r3, addr) \
    asm volatile("ldmatrix.sync.aligned.m8n8.x4.shared.b16 {%0,%1,%2,%3}, [%4];" \
        : "=r"(r0), "=r"(r1), "=r"(r2), "=r"(r3) : "r"(addr))

// stage one 32KB chunk with 256 threads
__device__ __forceinline__ void stage32(char* dst, const __nv_bfloat16* src, int tid) {
    const char* s = (const char*)src;
    #pragma unroll
    for (int i = 0; i < 8; i++) cpab(dst + tid*16 + i*4096, s + tid*16 + i*4096);
}
__device__ __forceinline__ int imgoff(int n, int k) {
    return n*64 + (((k >> 3) ^ (n & 7)) << 3) + (k & 7);
}

// ---------------- preprocessing (3 launches, coalesced) ----------------
__global__ void prep_scale(const float* __restrict__ gs) {
    __shared__ float red[256];
    int l = blockIdx.x, d = threadIdx.x;
    float x  = 0.5f * gs[l*Dd + d];
    float sp = (x > 20.f) ? x : log1pf(expf(x));
    float s  = 0.2f * sp;
    g_scale[l*Dd + d] = s;
    red[d] = logf(s);
    __syncthreads();
    #pragma unroll
    for (int o = 128; o; o >>= 1) { if (d < o) red[d] += red[d + o]; __syncthreads(); }
    if (d == 0) g_sumlog[l] = red[0];
}
#define W1T_CNT (Lc*256*16)
#define W2T_CNT (Lc*256*32)
#define WHT_CNT (256*32)
__global__ void prep_wimg(const float* __restrict__ W1, const float* __restrict__ W2,
                          const float* __restrict__ Wh1) {
    int idx = blockIdx.x * 256 + threadIdx.x;
    if (idx < W1T_CNT) {
        int n = idx & 255, ko = ((idx >> 8) & 15) * 8, l = idx >> 12;
        __nv_bfloat16 v[8];
        #pragma unroll
        for (int j = 0; j < 8; j++)
            v[j] = __float2bfloat16(W1[((size_t)l*128 + ko + j)*256 + n]);
        *(uint4*)&g_w1t[(size_t)l*32768 + (ko>>6)*16384 + imgoff(n, ko & 63)] = *(uint4*)v;
    } else if (idx < W1T_CNT + W2T_CNT) {
        int j2 = idx - W1T_CNT;
        int n = j2 & 255, ko = ((j2 >> 8) & 31) * 8, l = j2 >> 13;
        int jr = ((n & 127) >> 4) * 32 + ((n >> 7) << 4) + (n & 15);
        __nv_bfloat16 v[8];
        #pragma unroll
        for (int j = 0; j < 8; j++)
            v[j] = __float2bfloat16(W2[((size_t)l*256 + ko + j)*256 + n]);
        *(uint4*)&g_w2t[(size_t)l*65536 + (ko>>6)*16384 + imgoff(jr, ko & 63)] = *(uint4*)v;
    } else if (idx < W1T_CNT + W2T_CNT + WHT_CNT) {
        int j2 = idx - (W1T_CNT + W2T_CNT);
        int n = j2 & 255, ko = (j2 >> 8) * 8;
        __nv_bfloat16 vh[8], vl[8];
        #pragma unroll
        for (int j = 0; j < 8; j++) {
            float v = Wh1[((size_t)(ko + j))*256 + n];
            vh[j] = __float2bfloat16(v);
            vl[j] = __float2bfloat16(v - __bfloat162float(vh[j]));
        }
        size_t o = (size_t)(ko>>6)*16384 + imgoff(n, ko & 63);
        *(uint4*)&g_whh[o] = *(uint4*)vh;
        *(uint4*)&g_whl[o] = *(uint4*)vl;
    }
}
#define PT_CNT (Lc*256*32)
__global__ void prep_pimg(const float* __restrict__ P, const float* __restrict__ go) {
    int idx = blockIdx.x * 256 + threadIdx.x;
    if (idx < PT_CNT) {
        int ko = (idx & 31) * 8, n = (idx >> 5) & 255, l = idx >> 13;
        __nv_bfloat16 vh[8], vl[8];
        #pragma unroll
        for (int j = 0; j < 8; j++) {
            float v = P[((size_t)l*256 + n)*256 + ko + j] * g_scale[l*Dd + ko + j];
            vh[j] = __float2bfloat16(v);
            vl[j] = __float2bfloat16(v - __bfloat162float(vh[j]));
        }
        size_t o = (size_t)l*65536 + (ko>>6)*16384 + imgoff(n, ko & 63);
        *(uint4*)&g_ph[o] = *(uint4*)vh;
        *(uint4*)&g_pl[o] = *(uint4*)vl;
    } else if (idx < PT_CNT + Lc*256) {
        int j = idx - PT_CNT;
        int l = j >> 8, n = j & 255;
        const float* pr = P + ((size_t)l*256 + n)*256;
        const float* o  = go + l*Dd;
        float acc = 0.f;
        for (int k = 0; k < 256; k++) acc += o[k] * pr[k];
        g_po[l*Dd + n] = acc;
    }
}

// single-term pass: cacc += A(achunk) @ B
#define PASS_1T(AbaseU, achunk, BbufU) do {                                          \
    _Pragma("unroll")                                                                \
    for (int ks = 0; ks < 64; ks += 16) {                                            \
        int gA = ((achunk) << 3) + (ks >> 3) + laneHi;                               \
        uint32_t A_[2][4], B_[2][4];                                                 \
        _Pragma("unroll")                                                            \
        for (int mt = 0; mt < 2; mt++)                                               \
            LDSM4(A_[mt][0], A_[mt][1], A_[mt][2], A_[mt][3],                        \
                  (AbaseU) + (uint32_t)(mt*16*512 + aRowB + ((gA ^ key) << 4)));     \
        uint32_t bsw_ = (uint32_t)(((((ks >> 3) + bsel) ^ key) << 4));               \
        LDSM4(B_[0][0], B_[0][1], B_[0][2], B_[0][3], (BbufU) + (uint32_t)bRow0 + bsw_); \
        LDSM4(B_[1][0], B_[1][1], B_[1][2], B_[1][3], (BbufU) + (uint32_t)bRow1 + bsw_); \
        _Pragma("unroll")                                                            \
        for (int p = 0; p < 2; p++)                                                  \
            _Pragma("unroll")                                                        \
            for (int q = 0; q < 2; q++) {                                            \
                int nt = p*2 + q;                                                    \
                MMA(cacc[0][nt], A_[0][0], A_[0][1], A_[0][2], A_[0][3], B_[p][q*2], B_[p][q*2+1]); \
                MMA(cacc[1][nt], A_[1][0], A_[1][1], A_[1][2], A_[1][3], B_[p][q*2], B_[p][q*2+1]); \
            }                                                                        \
    }                                                                                \
} while (0)

// two-term pass: cacc += Ah(achunk)@B + Al(achunk)@B
#define PASS_2T(achunk, BbufU) do {                                                  \
    _Pragma("unroll")                                                                \
    for (int ks = 0; ks < 64; ks += 16) {                                            \
        int gA = ((achunk) << 3) + (ks >> 3) + laneHi;                               \
        uint32_t Ah_[2][4], Al_[2][4], B_[2][4];                                     \
        _Pragma("unroll")                                                            \
        for (int mt = 0; mt < 2; mt++) {                                             \
            uint32_t ab_ = (uint32_t)(mt*16*512 + aRowB + ((gA ^ key) << 4));        \
            LDSM4(Ah_[mt][0], Ah_[mt][1], Ah_[mt][2], Ah_[mt][3], XHI + ab_);        \
            LDSM4(Al_[mt][0], Al_[mt][1], Al_[mt][2], Al_[mt][3], XLO + ab_);        \
        }                                                                            \
        uint32_t bsw_ = (uint32_t)(((((ks >> 3) + bsel) ^ key) << 4));               \
        LDSM4(B_[0][0], B_[0][1], B_[0][2], B_[0][3], (BbufU) + (uint32_t)bRow0 + bsw_); \
        LDSM4(B_[1][0], B_[1][1], B_[1][2], B_[1][3], (BbufU) + (uint32_t)bRow1 + bsw_); \
        _Pragma("unroll")                                                            \
        for (int p = 0; p < 2; p++)                                                  \
            _Pragma("unroll")                                                        \
            for (int q = 0; q < 2; q++) {                                            \
                int nt = p*2 + q;                                                    \
                _Pragma("unroll")                                                    \
                for (int mt = 0; mt < 2; mt++) {                                     \
                    MMA(cacc[mt][nt], Ah_[mt][0], Ah_[mt][1], Ah_[mt][2], Ah_[mt][3], B_[p][q*2], B_[p][q*2+1]); \
                    MMA(cacc[mt][nt], Al_[mt][0], Al_[mt][1], Al_[mt][2], Al_[mt][3], B_[p][q*2], B_[p][q*2+1]); \
                }                                                                    \
            }                                                                        \
    }                                                                                \
} while (0)

#define PIPE_STAGE(srcptr) do {                                                      \
    CP_WAIT0; __syncthreads();                                                       \
    stage32(bw + (cb ^ 32768u), (srcptr), tid); CP_COMMIT;                           \
} while (0)

#define INIT_ACC_G(bias) do {                                                        \
    _Pragma("unroll")                                                                \
    for (int nt = 0; nt < 4; nt++) {                                                 \
        int c_ = c_base + nt*8;                                                      \
        float f0_ = __ldg((bias) + c_), f1_ = __ldg((bias) + c_ + 1);                \
        _Pragma("unroll")                                                            \
        for (int mt = 0; mt < 2; mt++) {                                             \
            cacc[mt][nt][0] = f0_; cacc[mt][nt][1] = f1_;                            \
            cacc[mt][nt][2] = f0_; cacc[mt][nt][3] = f1_;                            \
        }                                                                            \
    }                                                                                \
} while (0)

// ---------------- mega-fused: flow(8 layers) + log_px + head GEMM ----------------
__global__ void __launch_bounds__(NTHR, 2) flow_fused(
    const float* __restrict__ xin, float* __restrict__ hout,
    const float* __restrict__ b1, const float* __restrict__ b2,
    const float* __restrict__ bh1, float* __restrict__ logpx)
{
    extern __shared__ char smem[];
    const uint32_t su = (uint32_t)__cvta_generic_to_shared(smem);
    const uint32_t XHI = su + XHIo, XLO = su + XLOo, HBu = su + HBo, BWu = su + BWo;
    char* bw = smem + BWo;
    float* HBf = (float*)(smem + HBo);

    const int tid = threadIdx.x, lane = tid & 31;
    const int warpN = tid >> 5;
    const int g = lane >> 2, t = lane & 3;
    const int n0 = warpN * 32;
    const int laneHi = lane >> 4;
    const int key = lane & 7;
    const int aRowB = (lane & 15) * 512;
    const int nloc = ((lane >> 4) << 3) + (lane & 7);
    const int bRow0 = (n0 + nloc) * 128, bRow1 = (n0 + 16 + nloc) * 128;
    const int bsel = (lane >> 3) & 1;
    const int c_base = n0 + 2*t;

    uint32_t cb = 0;
    stage32(bw, g_w1t, tid); CP_COMMIT;

    {
        const float4* src = (const float4*)(xin + (size_t)blockIdx.x * MROW * Dd);
        #pragma unroll
        for (int i = tid; i < MROW * Dd / 4; i += NTHR) {
            int r = i >> 6, c = (i & 63) * 4;
            float4 v = src[i];
            uint32_t h0, l0, h1, l1;
            split2t(v.x, v.y, h0, l0);
            split2t(v.z, v.w, h1, l1);
            int off = r*512 + (((c >> 3) ^ (r & 7)) << 4) + (c & 7)*2;
            *(uint2*)(smem + XHIo + off) = make_uint2(h0, h1);
            *(uint2*)(smem + XLOo + off) = make_uint2(l0, l1);
        }
    }

    float cacc[2][4][4];
    float ldacc = 0.f;

    #pragma unroll 1
    for (int layer = 0; layer < Lc; layer++) {
        const float* bb2 = b2 + layer*Dd;
        const __nv_bfloat16* w1img = g_w1t + (size_t)layer*32768;
        const __nv_bfloat16* w2img = g_w2t + (size_t)layer*65536;
        const __nv_bfloat16* phimg = g_ph  + (size_t)layer*65536;
        const __nv_bfloat16* plimg = g_pl  + (size_t)layer*65536;
        const __nv_bfloat16* nxt0 = (layer + 1 < Lc) ? g_w1t + (size_t)(layer+1)*32768 : g_whh;

        // ===== GEMM1 (2 chunks) =====
        INIT_ACC_G(b1 + layer*Dd);
        PIPE_STAGE(w1img + 16384);
        PASS_1T(XHI, 0, BWu + cb); cb ^= 32768u;
        PIPE_STAGE(w2img);
        PASS_1T(XHI, 1, BWu + cb); cb ^= 32768u;
        #pragma unroll
        for (int nt = 0; nt < 4; nt++) {
            int c = c_base + nt*8;
            int csw = ((c >> 3) ^ g) << 4;
            #pragma unroll
            for (int mt = 0; mt < 2; mt++) {
                int r = mt*16 + g;
                float* cf = cacc[mt][nt];
                *(uint32_t*)(smem + HBo + r*512     + csw + 4*t) =
                    packbf2(fmaxf(cf[0], 0.f), fmaxf(cf[1], 0.f));
                *(uint32_t*)(smem + HBo + (r+8)*512 + csw + 4*t) =
                    packbf2(fmaxf(cf[2], 0.f), fmaxf(cf[3], 0.f));
            }
        }

        // ===== GEMM2 (4 chunks, output cols permuted) =====
        #pragma unroll
        for (int nt = 0; nt < 4; nt++) {
            int p = nt >> 1, q = nt & 1;
            int c2 = p*128 + warpN*16 + q*8 + 2*t;
            float f0 = __ldg(bb2 + c2), f1 = __ldg(bb2 + c2 + 1);
            #pragma unroll
            for (int mt = 0; mt < 2; mt++) {
                cacc[mt][nt][0] = f0; cacc[mt][nt][1] = f1;
                cacc[mt][nt][2] = f0; cacc[mt][nt][3] = f1;
            }
        }
        #pragma unroll
        for (int c2 = 0; c2 < 4; c2++) {
            PIPE_STAGE((c2 < 3) ? (w2img + (c2+1)*16384) : phimg);
            PASS_1T(HBu, c2, BWu + cb); cb ^= 32768u;
        }

        // ===== coupling epilogue =====
        float lds0, lds1, lds2, lds3;
        {
            float lds[2][2] = {{0.f, 0.f}, {0.f, 0.f}};
            #pragma unroll
            for (int q = 0; q < 2; q++) {
                int cx = 128 + warpN*16 + q*8 + 2*t;
                #pragma unroll
                for (int mt = 0; mt < 2; mt++) {
                    #pragma unroll
                    for (int half = 0; half < 2; half++) {
                        int i0 = half*2, r = mt*16 + g + half*8;
                        float s0 = fast_tanh_scaled(cacc[mt][q][i0]);
                        float s1 = fast_tanh_scaled(cacc[mt][q][i0 + 1]);
                        lds[mt][half] += s0 + s1;
                        float a20 = 0.1f * cacc[mt][2 + q][i0];
                        float a21 = 0.1f * cacc[mt][2 + q][i0 + 1];
                        int xo = r*512 + (((cx >> 3) ^ g) << 4) + 4*t;
                        float2 hv = unpackbf2(*(uint32_t*)(smem + XHIo + xo));
                        float2 lv = unpackbf2(*(uint32_t*)(smem + XLOo + xo));
                        float v0 = (hv.x + lv.x) * __expf(s0) + a20;
                        float v1 = (hv.y + lv.y) * __expf(s1) + a21;
                        uint32_t hw, lw; split2t(v0, v1, hw, lw);
                        *(uint32_t*)(smem + XHIo + xo) = hw;
                        *(uint32_t*)(smem + XLOo + xo) = lw;
                    }
                }
            }
            #pragma unroll
            for (int mt = 0; mt < 2; mt++)
                #pragma unroll
                for (int half = 0; half < 2; half++) {
                    float v = lds[mt][half];
                    v += __shfl_xor_sync(0xffffffffu, v, 1);
                    v += __shfl_xor_sync(0xffffffffu, v, 2);
                    lds[mt][half] = v;
                }
            lds0 = lds[0][0]; lds1 = lds[0][1]; lds2 = lds[1][0]; lds3 = lds[1][1];
        }

        // ===== GEMM3 (4 chunks x {hi 2-term, lo 1-term}) =====
        INIT_ACC_G(g_po + layer*Dd);
        #pragma unroll
        for (int c3 = 0; c3 < 4; c3++) {
            PIPE_STAGE(plimg + c3*16384);
            if (c3 == 0 && t == 0) {
                HBf[(g)*8 + warpN]      = lds0;
                HBf[(g + 8)*8 + warpN]  = lds1;
                HBf[(16 + g)*8 + warpN] = lds2;
                HBf[(24 + g)*8 + warpN] = lds3;
            }
            PASS_2T(c3, BWu + cb); cb ^= 32768u;
            PIPE_STAGE((c3 < 3) ? (phimg + (c3+1)*16384) : nxt0);
            PASS_1T(XHI, c3, BWu + cb); cb ^= 32768u;
        }
        __syncthreads();

        if (tid < MROW) {
            float rs = 0.f;
            #pragma unroll
            for (int w = 0; w < 8; w++) rs += HBf[tid*8 + w];
            ldacc += rs + g_sumlog[layer];
        }
        #pragma unroll
        for (int nt = 0; nt < 4; nt++) {
            int c = c_base + nt*8;
            int csw = ((c >> 3) ^ g) << 4;
            #pragma unroll
            for (int mt = 0; mt < 2; mt++) {
                float* cf = cacc[mt][nt];
                #pragma unroll
                for (int half = 0; half < 2; half++) {
                    int r = mt*16 + g + half*8;
                    uint32_t hw, lw;
                    split2t(cf[half*2 + 0], cf[half*2 + 1], hw, lw);
                    *(uint32_t*)(smem + XHIo + r*512 + csw + 4*t) = hw;
                    *(uint32_t*)(smem + XLOo + r*512 + csw + 4*t) = lw;
                }
            }
        }
    }

    // ===================== fused tail: log_px =====================
    {
        float z2[2][2];
        #pragma unroll
        for (int mt = 0; mt < 2; mt++)
            #pragma unroll
            for (int half = 0; half < 2; half++) {
                float s = 0.f;
                #pragma unroll
                for (int nt = 0; nt < 4; nt++) {
                    float a = cacc[mt][nt][half*2 + 0], b = cacc[mt][nt][half*2 + 1];
                    s += a*a + b*b;
                }
                s += __shfl_xor_sync(0xffffffffu, s, 1);
                s += __shfl_xor_sync(0xffffffffu, s, 2);
                z2[mt][half] = s;
            }
        __syncthreads();
        if (t == 0) {
            #pragma unroll
            for (int mt = 0; mt < 2; mt++)
                #pragma unroll
                for (int half = 0; half < 2; half++) {
                    int r = mt*16 + g + half*8;
                    HBf[r*8 + warpN] = z2[mt][half];
                }
        }
        __syncthreads();
        if (tid < MROW) {
            float ss = 0.f;
            #pragma unroll
            for (int w = 0; w < 8; w++) ss += HBf[tid*8 + w];
            logpx[(size_t)blockIdx.x * MROW + tid] =
                (DGCONST - 0.5f*ss + ldacc) * (1.0f/Dd);
        }
    }

    // ===================== head GEMM: h = z @ Wh1 (3-term) + bh1 =====================
    {
        INIT_ACC_G(bh1);
        #pragma unroll
        for (int c = 0; c < 4; c++) {
            PIPE_STAGE(g_whl + c*16384);
            PASS_2T(c, BWu + cb); cb ^= 32768u;
            CP_WAIT0; __syncthreads();
            if (c < 3) { stage32(bw + (cb ^ 32768u), g_whh + (c+1)*16384, tid); CP_COMMIT; }
            PASS_1T(XHI, c, BWu + cb); cb ^= 32768u;
        }
        __syncthreads();

        float* stg = (float*)smem;     // [32][264] fp32 overlay
        #pragma unroll
        for (int mt = 0; mt < 2; mt++)
            #pragma unroll
            for (int half = 0; half < 2; half++) {
                int rl = mt*16 + g + half*8;
                int r  = blockIdx.x * MROW + rl;
                #pragma unroll
                for (int nt = 0; nt < 4; nt++) {
                    int c = c_base + nt*8;
                    float* cf = cacc[mt][nt];
                    float v0 = cf[half*2 + 0];
                    float v1 = cf[half*2 + 1];
                    *(float2*)(hout + (size_t)r*Dd + c) = make_float2(v0, v1);
                    stg[(size_t)rl*264 + c]     = v0;
                    stg[(size_t)rl*264 + c + 1] = v1;
                }
            }
        __syncthreads();
        if (tid < Dd) {
            float s = 0.f, q = 0.f;
            #pragma unroll 4
            for (int r = 0; r < MROW; r++) {
                float v = stg[(size_t)r*264 + tid];
                s += v; q += v * v;
            }
            g_part[(size_t)blockIdx.x*2*Dd + tid]      = s;
            g_part[(size_t)blockIdx.x*2*Dd + Dd + tid] = q;
        }
    }
}

// ---------------- BN stats fold (two-stage parallel reduction) ----------------
__global__ void __launch_bounds__(512) stats1_kernel() {
    int b = blockIdx.x, c = threadIdx.x;       // c in [0, 512)
    float s = 0.f;
    int i0 = b * (NBLK/64);
    #pragma unroll 4
    for (int i = 0; i < NBLK/64; i++)
        s += g_part[(size_t)(i0 + i)*2*Dd + c];
    g_part2[b*2*Dd + c] = s;
}
__global__ void stats2_kernel(const float* __restrict__ gamma, const float* __restrict__ beta) {
    int c = threadIdx.x;
    float s = 0.f, q = 0.f;
    #pragma unroll
    for (int i = 0; i < 64; i++) {
        s += g_part2[i*2*Dd + c];
        q += g_part2[i*2*Dd + Dd + c];
    }
    float mu  = s * (1.f/Bsz);
    float var = q * (1.f/Bsz) - mu*mu;
    float a = gamma[c] * rsqrtf(var + BN_EPS);
    g_stats[c]      = a;
    g_stats[Dd + c] = beta[c] - mu * a;
}

// ---------------- logits ----------------
__global__ void __launch_bounds__(256) logits_kernel(
    const float* __restrict__ h, const float* __restrict__ Wh2,
    const float* __restrict__ bh2, float* __restrict__ out)
{
    __shared__ float w2s[Dd*NCc];
    __shared__ float As[Dd], Bs[Dd];
    int tid = threadIdx.x;
    for (int i = tid; i < Dd*NCc; i += 256) w2s[i] = Wh2[i];
    if (tid < Dd) { As[tid] = g_stats[tid]; Bs[tid] = g_stats[Dd + tid]; }
    __syncthreads();

    int warp = tid >> 5, lane = tid & 31;
    size_t row = (size_t)blockIdx.x * 8 + warp;
    const float4* hr = (const float4*)(h + row*Dd);
    float4 v0 = hr[lane*2], v1 = hr[lane*2 + 1];
    int k0 = lane * 8;
    float hn[8];
    hn[0] = fmaxf(v0.x*As[k0+0] + Bs[k0+0], 0.f);
    hn[1] = fmaxf(v0.y*As[k0+1] + Bs[k0+1], 0.f);
    hn[2] = fmaxf(v0.z*As[k0+2] + Bs[k0+2], 0.f);
    hn[3] = fmaxf(v0.w*As[k0+3] + Bs[k0+3], 0.f);
    hn[4] = fmaxf(v1.x*As[k0+4] + Bs[k0+4], 0.f);
    hn[5] = fmaxf(v1.y*As[k0+5] + Bs[k0+5], 0.f);
    hn[6] = fmaxf(v1.z*As[k0+6] + Bs[k0+6], 0.f);
    hn[7] = fmaxf(v1.w*As[k0+7] + Bs[k0+7], 0.f);

    float acc[NCc];
    #pragma unroll
    for (int c = 0; c < NCc; c++) acc[c] = 0.f;
    #pragma unroll
    for (int kk = 0; kk < 8; kk++) {
        float x = hn[kk];
        const float* wr = &w2s[(k0+kk)*NCc];
        #pragma unroll
        for (int c = 0; c < NCc; c++) acc[c] += x * wr[c];
    }
    #pragma unroll
    for (int c = 0; c < NCc; c++) {
        #pragma unroll
        for (int o = 16; o; o >>= 1) acc[c] += __shfl_down_sync(0xffffffffu, acc[c], o);
    }
    if (lane == 0) {
        #pragma unroll
        for (int c = 0; c < NCc; c++) out[row*NCc + c] = acc[c] + __ldg(bh2 + c);
    }
}

// ---------------- launch ----------------
extern "C" void kernel_launch(void* const* d_in, const int* in_sizes, int n_in,
                              void* d_out, int out_size)
{
    const float* feat  = (const float*)d_in[0];
    const float* W1    = (const float*)d_in[1];
    const float* b1    = (const float*)d_in[2];
    const float* W2    = (const float*)d_in[3];
    const float* b2    = (const float*)d_in[4];
    const float* gs    = (const float*)d_in[5];
    const float* go    = (const float*)d_in[6];
    const float* P     = (const float*)d_in[7];
    const float* Wh1   = (const float*)d_in[8];
    const float* bh1   = (const float*)d_in[9];
    const float* gamma = (const float*)d_in[10];
    const float* beta  = (const float*)d_in[11];
    const float* Wh2   = (const float*)d_in[12];
    const float* bh2   = (const float*)d_in[13];
    float* out = (float*)d_out;

    cudaFuncSetAttribute(flow_fused, cudaFuncAttributeMaxDynamicSharedMemorySize, SMEMSZ);

    float* bufA = nullptr;
    cudaGetSymbolAddress((void**)&bufA, g_bufA);

    prep_scale<<<Lc, 256>>>(gs);
    prep_wimg<<<(W1T_CNT + W2T_CNT + WHT_CNT + 255)/256, 256>>>(W1, W2, Wh1);
    prep_pimg<<<(PT_CNT + Lc*256 + 255)/256, 256>>>(P, go);

    flow_fused<<<NBLK, NTHR, SMEMSZ>>>(feat, bufA, b1, b2, bh1, out);

    stats1_kernel<<<64, 512>>>();
    stats2_kernel<<<1, 256>>>(gamma, beta);
    logits_kernel<<<Bsz/8, 256>>>(bufA, Wh2, bh2, out + Bsz);
}

// round 17
// speedup vs baseline: 1.1796x; 1.0130x over previous
#include <cuda_runtime.h>
#include <cuda_bf16.h>
#include <math.h>
#include <stdint.h>

// ---------------- problem constants ----------------
#define Bsz   131072
#define Dd    256
#define Lc    8
#define NCc   10
#define BN_EPS 1e-5f
#define DGCONST -235.24826450039622f   // D * GCONST

#define MROW  32
#define NTHR  256
#define NBLK  (Bsz/MROW)      // 4096 CTAs

// smem: XHI 16K | XLO 16K | HB 16K | BW 2x32K  = 112KB/CTA, 2 CTAs/SM
#define XHIo 0
#define XLOo 16384
#define HBo  32768
#define BWo  49152
#define SMEMSZ 114688

// ---------------- static device scratch ----------------
__device__ float g_bufA[(size_t)Bsz*Dd];          // h
__device__ float g_scale[Lc*Dd];
__device__ float g_sumlog[Lc];
__device__ float g_po[Lc*Dd];
__device__ float g_part[(size_t)NBLK*2*Dd];
__device__ float g_part2[64*2*Dd];
__device__ float g_stats[2*Dd];
// pre-swizzled bf16 weight images
__device__ __nv_bfloat16 g_w1t[(size_t)Lc*32768];   // 2 chunks/layer (hi only)
__device__ __nv_bfloat16 g_w2t[(size_t)Lc*65536];   // 4 chunks/layer, column-PERMUTED
// interleaved hi/lo images: 8 chunks/layer, each chunk = 256 rows x [hi k32 | lo k32]
__device__ __nv_bfloat16 g_pil[(size_t)Lc*131072];  // P' = P*diag(scale)
__device__ __nv_bfloat16 g_whi[131072];             // Wh1

// ---------------- helpers ----------------
__device__ __forceinline__ uint32_t packbf2(float a, float b) {
    __nv_bfloat162 t = __floats2bfloat162_rn(a, b);
    return *(uint32_t*)&t;
}
__device__ __forceinline__ float2 unpackbf2(uint32_t w) {
    __nv_bfloat162 t = *(__nv_bfloat162*)&w;
    return __bfloat1622float2(t);
}
__device__ __forceinline__ void split2t(float a, float b, uint32_t& hw, uint32_t& lw) {
    uint32_t ia = __float_as_uint(a), ib = __float_as_uint(b);
    asm("prmt.b32 %0, %1, %2, 0x7632;" : "=r"(hw) : "r"(ia), "r"(ib));
    float ha = __uint_as_float(ia & 0xFFFF0000u);
    float hb = __uint_as_float(ib & 0xFFFF0000u);
    uint32_t il = __float_as_uint(a - ha), jl = __float_as_uint(b - hb);
    asm("prmt.b32 %0, %1, %2, 0x7632;" : "=r"(lw) : "r"(il), "r"(jl));
}
__device__ __forceinline__ float fast_tanh_scaled(float a) {
    float e = __expf(-0.2f * a);
    return 1.9f * __fdividef(1.f - e, 1.f + e);
}
__device__ __forceinline__ void cpab(void* dst_smem, const void* src) {
    unsigned s = (unsigned)__cvta_generic_to_shared(dst_smem);
    asm volatile("cp.async.cg.shared.global [%0], [%1], 16;" :: "r"(s), "l"(src));
}
#define CP_COMMIT asm volatile("cp.async.commit_group;")
#define CP_WAIT0  asm volatile("cp.async.wait_group 0;")

#define MMA(cd, a0, a1, a2, a3, b0, b1) \
    asm volatile("mma.sync.aligned.m16n8k16.row.col.f32.bf16.bf16.f32 " \
        "{%0,%1,%2,%3}, {%4,%5,%6,%7}, {%8,%9}, {%0,%1,%2,%3};" \
        : "+f"((cd)[0]), "+f"((cd)[1]), "+f"((cd)[2]), "+f"((cd)[3]) \
        : "r"(a0), "r"(a1), "r"(a2), "r"(a3), "r"(b0), "r"(b1))

#define LDSM4(r0, r1, r2, r3, addr) \
    asm volatile("ldmatrix.sync.aligned.m8n8.x4.shared.b16 {%0,%1,%2,%3}, [%4];" \
        : "=r"(r0), "=r"(r1), "=r"(r2), "=r"(r3) : "r"(addr))

// stage one 32KB chunk with 256 threads
__device__ __forceinline__ void stage32(char* dst, const __nv_bfloat16* src, int tid) {
    const char* s = (const char*)src;
    #pragma unroll
    for (int i = 0; i < 8; i++) cpab(dst + tid*16 + i*4096, s + tid*16 + i*4096);
}
__device__ __forceinline__ int imgoff(int n, int k) {
    return n*64 + (((k >> 3) ^ (n & 7)) << 3) + (k & 7);
}

// ---------------- preprocessing (3 launches, coalesced) ----------------
__global__ void prep_scale(const float* __restrict__ gs) {
    __shared__ float red[256];
    int l = blockIdx.x, d = threadIdx.x;
    float x  = 0.5f * gs[l*Dd + d];
    float sp = (x > 20.f) ? x : log1pf(expf(x));
    float s  = 0.2f * sp;
    g_scale[l*Dd + d] = s;
    red[d] = logf(s);
    __syncthreads();
    #pragma unroll
    for (int o = 128; o; o >>= 1) { if (d < o) red[d] += red[d + o]; __syncthreads(); }
    if (d == 0) g_sumlog[l] = red[0];
}
#define W1T_CNT (Lc*256*16)
#define W2T_CNT (Lc*256*32)
#define WHT_CNT (256*32)
__global__ void prep_wimg(const float* __restrict__ W1, const float* __restrict__ W2,
                          const float* __restrict__ Wh1) {
    int idx = blockIdx.x * 256 + threadIdx.x;
    if (idx < W1T_CNT) {
        int n = idx & 255, ko = ((idx >> 8) & 15) * 8, l = idx >> 12;
        __nv_bfloat16 v[8];
        #pragma unroll
        for (int j = 0; j < 8; j++)
            v[j] = __float2bfloat16(W1[((size_t)l*128 + ko + j)*256 + n]);
        *(uint4*)&g_w1t[(size_t)l*32768 + (ko>>6)*16384 + imgoff(n, ko & 63)] = *(uint4*)v;
    } else if (idx < W1T_CNT + W2T_CNT) {
        int j2 = idx - W1T_CNT;
        int n = j2 & 255, ko = ((j2 >> 8) & 31) * 8, l = j2 >> 13;
        int jr = ((n & 127) >> 4) * 32 + ((n >> 7) << 4) + (n & 15);
        __nv_bfloat16 v[8];
        #pragma unroll
        for (int j = 0; j < 8; j++)
            v[j] = __float2bfloat16(W2[((size_t)l*256 + ko + j)*256 + n]);
        *(uint4*)&g_w2t[(size_t)l*65536 + (ko>>6)*16384 + imgoff(jr, ko & 63)] = *(uint4*)v;
    } else if (idx < W1T_CNT + W2T_CNT + WHT_CNT) {
        int j2 = idx - (W1T_CNT + W2T_CNT);
        int n = j2 & 255, ko = (j2 >> 8) * 8;
        __nv_bfloat16 vh[8], vl[8];
        #pragma unroll
        for (int j = 0; j < 8; j++) {
            float v = Wh1[((size_t)(ko + j))*256 + n];
            vh[j] = __float2bfloat16(v);
            vl[j] = __float2bfloat16(v - __bfloat162float(vh[j]));
        }
        size_t base = (size_t)(ko>>5)*16384;
        int pos = ko & 31;
        *(uint4*)&g_whi[base + imgoff(n, pos)]      = *(uint4*)vh;
        *(uint4*)&g_whi[base + imgoff(n, 32 + pos)] = *(uint4*)vl;
    }
}
#define PT_CNT (Lc*256*32)
__global__ void prep_pimg(const float* __restrict__ P, const float* __restrict__ go) {
    int idx = blockIdx.x * 256 + threadIdx.x;
    if (idx < PT_CNT) {
        int ko = (idx & 31) * 8, n = (idx >> 5) & 255, l = idx >> 13;
        __nv_bfloat16 vh[8], vl[8];
        #pragma unroll
        for (int j = 0; j < 8; j++) {
            float v = P[((size_t)l*256 + n)*256 + ko + j] * g_scale[l*Dd + ko + j];
            vh[j] = __float2bfloat16(v);
            vl[j] = __float2bfloat16(v - __bfloat162float(vh[j]));
        }
        size_t base = (size_t)l*131072 + (size_t)(ko>>5)*16384;
        int pos = ko & 31;
        *(uint4*)&g_pil[base + imgoff(n, pos)]      = *(uint4*)vh;
        *(uint4*)&g_pil[base + imgoff(n, 32 + pos)] = *(uint4*)vl;
    } else if (idx < PT_CNT + Lc*256) {
        int j = idx - PT_CNT;
        int l = j >> 8, n = j & 255;
        const float* pr = P + ((size_t)l*256 + n)*256;
        const float* o  = go + l*Dd;
        float acc = 0.f;
        for (int k = 0; k < 256; k++) acc += o[k] * pr[k];
        g_po[l*Dd + n] = acc;
    }
}

// single-term pass over a 64-k chunk: cacc += A(achunk64) @ B
#define PASS_1T(AbaseU, achunk, BbufU) do {                                          \
    _Pragma("unroll")                                                                \
    for (int ks = 0; ks < 64; ks += 16) {                                            \
        int gA = ((achunk) << 3) + (ks >> 3) + laneHi;                               \
        uint32_t A_[2][4], B_[2][4];                                                 \
        _Pragma("unroll")                                                            \
        for (int mt = 0; mt < 2; mt++)                                               \
            LDSM4(A_[mt][0], A_[mt][1], A_[mt][2], A_[mt][3],                        \
                  (AbaseU) + (uint32_t)(mt*16*512 + aRowB + ((gA ^ key) << 4)));     \
        uint32_t bsw_ = (uint32_t)(((((ks >> 3) + bsel) ^ key) << 4));               \
        LDSM4(B_[0][0], B_[0][1], B_[0][2], B_[0][3], (BbufU) + (uint32_t)bRow0 + bsw_); \
        LDSM4(B_[1][0], B_[1][1], B_[1][2], B_[1][3], (BbufU) + (uint32_t)bRow1 + bsw_); \
        _Pragma("unroll")                                                            \
        for (int p = 0; p < 2; p++)                                                  \
            _Pragma("unroll")                                                        \
            for (int q = 0; q < 2; q++) {                                            \
                int nt = p*2 + q;                                                    \
                MMA(cacc[0][nt], A_[0][0], A_[0][1], A_[0][2], A_[0][3], B_[p][q*2], B_[p][q*2+1]); \
                MMA(cacc[1][nt], A_[1][0], A_[1][1], A_[1][2], A_[1][3], B_[p][q*2], B_[p][q*2+1]); \
            }                                                                        \
    }                                                                                \
} while (0)

// fused 3-term pass over a 32-k interleaved chunk:
// cacc += Ah@Bh + Al@Bh + Ah@Bl   (B image row = [hi granules 0..3 | lo granules 4..7])
#define PASS_3T(achunk32, BbufU) do {                                                \
    _Pragma("unroll")                                                                \
    for (int ks = 0; ks < 32; ks += 16) {                                            \
        int gA = ((achunk32) << 2) + (ks >> 3) + laneHi;                             \
        uint32_t Ah_[2][4], Al_[2][4], Bh_[2][4], Bl_[2][4];                         \
        _Pragma("unroll")                                                            \
        for (int mt = 0; mt < 2; mt++) {                                             \
            uint32_t ab_ = (uint32_t)(mt*16*512 + aRowB + ((gA ^ key) << 4));        \
            LDSM4(Ah_[mt][0], Ah_[mt][1], Ah_[mt][2], Ah_[mt][3], XHI + ab_);        \
            LDSM4(Al_[mt][0], Al_[mt][1], Al_[mt][2], Al_[mt][3], XLO + ab_);        \
        }                                                                            \
        int bg_ = (ks >> 3) + bsel;                                                  \
        uint32_t bswh_ = (uint32_t)(((bg_ ^ key) << 4));                             \
        uint32_t bswl_ = (uint32_t)((((bg_ + 4) ^ key) << 4));                       \
        LDSM4(Bh_[0][0], Bh_[0][1], Bh_[0][2], Bh_[0][3], (BbufU) + (uint32_t)bRow0 + bswh_); \
        LDSM4(Bh_[1][0], Bh_[1][1], Bh_[1][2], Bh_[1][3], (BbufU) + (uint32_t)bRow1 + bswh_); \
        LDSM4(Bl_[0][0], Bl_[0][1], Bl_[0][2], Bl_[0][3], (BbufU) + (uint32_t)bRow0 + bswl_); \
        LDSM4(Bl_[1][0], Bl_[1][1], Bl_[1][2], Bl_[1][3], (BbufU) + (uint32_t)bRow1 + bswl_); \
        _Pragma("unroll")                                                            \
        for (int p = 0; p < 2; p++)                                                  \
            _Pragma("unroll")                                                        \
            for (int q = 0; q < 2; q++) {                                            \
                int nt = p*2 + q;                                                    \
                _Pragma("unroll")                                                    \
                for (int mt = 0; mt < 2; mt++) {                                     \
                    MMA(cacc[mt][nt], Ah_[mt][0], Ah_[mt][1], Ah_[mt][2], Ah_[mt][3], Bh_[p][q*2], Bh_[p][q*2+1]); \
                    MMA(cacc[mt][nt], Al_[mt][0], Al_[mt][1], Al_[mt][2], Al_[mt][3], Bh_[p][q*2], Bh_[p][q*2+1]); \
                    MMA(cacc[mt][nt], Ah_[mt][0], Ah_[mt][1], Ah_[mt][2], Ah_[mt][3], Bl_[p][q*2], Bl_[p][q*2+1]); \
                }                                                                    \
            }                                                                        \
    }                                                                                \
} while (0)

#define PIPE_STAGE(srcptr) do {                                                      \
    CP_WAIT0; __syncthreads();                                                       \
    stage32(bw + (cb ^ 32768u), (srcptr), tid); CP_COMMIT;                           \
} while (0)

#define INIT_ACC_G(bias) do {                                                        \
    _Pragma("unroll")                                                                \
    for (int nt = 0; nt < 4; nt++) {                                                 \
        int c_ = c_base + nt*8;                                                      \
        float f0_ = __ldg((bias) + c_), f1_ = __ldg((bias) + c_ + 1);                \
        _Pragma("unroll")                                                            \
        for (int mt = 0; mt < 2; mt++) {                                             \
            cacc[mt][nt][0] = f0_; cacc[mt][nt][1] = f1_;                            \
            cacc[mt][nt][2] = f0_; cacc[mt][nt][3] = f1_;                            \
        }                                                                            \
    }                                                                                \
} while (0)

// ---------------- mega-fused: flow(8 layers) + log_px + head GEMM ----------------
__global__ void __launch_bounds__(NTHR, 2) flow_fused(
    const float* __restrict__ xin, float* __restrict__ hout,
    const float* __restrict__ b1, const float* __restrict__ b2,
    const float* __restrict__ bh1, float* __restrict__ logpx)
{
    extern __shared__ char smem[];
    const uint32_t su = (uint32_t)__cvta_generic_to_shared(smem);
    const uint32_t XHI = su + XHIo, XLO = su + XLOo, HBu = su + HBo, BWu = su + BWo;
    char* bw = smem + BWo;
    float* HBf = (float*)(smem + HBo);

    const int tid = threadIdx.x, lane = tid & 31;
    const int warpN = tid >> 5;
    const int g = lane >> 2, t = lane & 3;
    const int n0 = warpN * 32;
    const int laneHi = lane >> 4;
    const int key = lane & 7;
    const int aRowB = (lane & 15) * 512;
    const int nloc = ((lane >> 4) << 3) + (lane & 7);
    const int bRow0 = (n0 + nloc) * 128, bRow1 = (n0 + 16 + nloc) * 128;
    const int bsel = (lane >> 3) & 1;
    const int c_base = n0 + 2*t;

    uint32_t cb = 0;
    stage32(bw, g_w1t, tid); CP_COMMIT;

    {
        const float4* src = (const float4*)(xin + (size_t)blockIdx.x * MROW * Dd);
        #pragma unroll
        for (int i = tid; i < MROW * Dd / 4; i += NTHR) {
            int r = i >> 6, c = (i & 63) * 4;
            float4 v = src[i];
            uint32_t h0, l0, h1, l1;
            split2t(v.x, v.y, h0, l0);
            split2t(v.z, v.w, h1, l1);
            int off = r*512 + (((c >> 3) ^ (r & 7)) << 4) + (c & 7)*2;
            *(uint2*)(smem + XHIo + off) = make_uint2(h0, h1);
            *(uint2*)(smem + XLOo + off) = make_uint2(l0, l1);
        }
    }

    float cacc[2][4][4];
    float ldacc = 0.f;

    #pragma unroll 1
    for (int layer = 0; layer < Lc; layer++) {
        const float* bb2 = b2 + layer*Dd;
        const __nv_bfloat16* w1img = g_w1t + (size_t)layer*32768;
        const __nv_bfloat16* w2img = g_w2t + (size_t)layer*65536;
        const __nv_bfloat16* pilimg = g_pil + (size_t)layer*131072;
        const __nv_bfloat16* nxt0 = (layer + 1 < Lc) ? g_w1t + (size_t)(layer+1)*32768 : g_whi;

        // ===== GEMM1 (2 chunks of 64k) =====
        INIT_ACC_G(b1 + layer*Dd);
        PIPE_STAGE(w1img + 16384);
        PASS_1T(XHI, 0, BWu + cb); cb ^= 32768u;
        PIPE_STAGE(w2img);
        PASS_1T(XHI, 1, BWu + cb); cb ^= 32768u;
        #pragma unroll
        for (int nt = 0; nt < 4; nt++) {
            int c = c_base + nt*8;
            int csw = ((c >> 3) ^ g) << 4;
            #pragma unroll
            for (int mt = 0; mt < 2; mt++) {
                int r = mt*16 + g;
                float* cf = cacc[mt][nt];
                *(uint32_t*)(smem + HBo + r*512     + csw + 4*t) =
                    packbf2(fmaxf(cf[0], 0.f), fmaxf(cf[1], 0.f));
                *(uint32_t*)(smem + HBo + (r+8)*512 + csw + 4*t) =
                    packbf2(fmaxf(cf[2], 0.f), fmaxf(cf[3], 0.f));
            }
        }

        // ===== GEMM2 (4 chunks of 64k, output cols permuted) =====
        #pragma unroll
        for (int nt = 0; nt < 4; nt++) {
            int p = nt >> 1, q = nt & 1;
            int c2 = p*128 + warpN*16 + q*8 + 2*t;
            float f0 = __ldg(bb2 + c2), f1 = __ldg(bb2 + c2 + 1);
            #pragma unroll
            for (int mt = 0; mt < 2; mt++) {
                cacc[mt][nt][0] = f0; cacc[mt][nt][1] = f1;
                cacc[mt][nt][2] = f0; cacc[mt][nt][3] = f1;
            }
        }
        #pragma unroll
        for (int c2 = 0; c2 < 4; c2++) {
            PIPE_STAGE((c2 < 3) ? (w2img + (c2+1)*16384) : pilimg);
            PASS_1T(HBu, c2, BWu + cb); cb ^= 32768u;
        }

        // ===== coupling epilogue =====
        float lds0, lds1, lds2, lds3;
        {
            float lds[2][2] = {{0.f, 0.f}, {0.f, 0.f}};
            #pragma unroll
            for (int q = 0; q < 2; q++) {
                int cx = 128 + warpN*16 + q*8 + 2*t;
                #pragma unroll
                for (int mt = 0; mt < 2; mt++) {
                    #pragma unroll
                    for (int half = 0; half < 2; half++) {
                        int i0 = half*2, r = mt*16 + g + half*8;
                        float s0 = fast_tanh_scaled(cacc[mt][q][i0]);
                        float s1 = fast_tanh_scaled(cacc[mt][q][i0 + 1]);
                        lds[mt][half] += s0 + s1;
                        float a20 = 0.1f * cacc[mt][2 + q][i0];
                        float a21 = 0.1f * cacc[mt][2 + q][i0 + 1];
                        int xo = r*512 + (((cx >> 3) ^ g) << 4) + 4*t;
                        float2 hv = unpackbf2(*(uint32_t*)(smem + XHIo + xo));
                        float2 lv = unpackbf2(*(uint32_t*)(smem + XLOo + xo));
                        float v0 = (hv.x + lv.x) * __expf(s0) + a20;
                        float v1 = (hv.y + lv.y) * __expf(s1) + a21;
                        uint32_t hw, lw; split2t(v0, v1, hw, lw);
                        *(uint32_t*)(smem + XHIo + xo) = hw;
                        *(uint32_t*)(smem + XLOo + xo) = lw;
                    }
                }
            }
            #pragma unroll
            for (int mt = 0; mt < 2; mt++)
                #pragma unroll
                for (int half = 0; half < 2; half++) {
                    float v = lds[mt][half];
                    v += __shfl_xor_sync(0xffffffffu, v, 1);
                    v += __shfl_xor_sync(0xffffffffu, v, 2);
                    lds[mt][half] = v;
                }
            lds0 = lds[0][0]; lds1 = lds[0][1]; lds2 = lds[1][0]; lds3 = lds[1][1];
        }

        // ===== GEMM3 (8 interleaved 32-k chunks, fused 3-term) =====
        INIT_ACC_G(g_po + layer*Dd);
        #pragma unroll
        for (int c3 = 0; c3 < 8; c3++) {
            PIPE_STAGE((c3 < 7) ? (pilimg + (c3+1)*16384) : nxt0);
            if (c3 == 0 && t == 0) {
                HBf[(g)*8 + warpN]      = lds0;
                HBf[(g + 8)*8 + warpN]  = lds1;
                HBf[(16 + g)*8 + warpN] = lds2;
                HBf[(24 + g)*8 + warpN] = lds3;
            }
            PASS_3T(c3, BWu + cb); cb ^= 32768u;
        }
        __syncthreads();

        if (tid < MROW) {
            float rs = 0.f;
            #pragma unroll
            for (int w = 0; w < 8; w++) rs += HBf[tid*8 + w];
            ldacc += rs + g_sumlog[layer];
        }
        #pragma unroll
        for (int nt = 0; nt < 4; nt++) {
            int c = c_base + nt*8;
            int csw = ((c >> 3) ^ g) << 4;
            #pragma unroll
            for (int mt = 0; mt < 2; mt++) {
                float* cf = cacc[mt][nt];
                #pragma unroll
                for (int half = 0; half < 2; half++) {
                    int r = mt*16 + g + half*8;
                    uint32_t hw, lw;
                    split2t(cf[half*2 + 0], cf[half*2 + 1], hw, lw);
                    *(uint32_t*)(smem + XHIo + r*512 + csw + 4*t) = hw;
                    *(uint32_t*)(smem + XLOo + r*512 + csw + 4*t) = lw;
                }
            }
        }
    }

    // ===================== fused tail: log_px =====================
    {
        float z2[2][2];
        #pragma unroll
        for (int mt = 0; mt < 2; mt++)
            #pragma unroll
            for (int half = 0; half < 2; half++) {
                float s = 0.f;
                #pragma unroll
                for (int nt = 0; nt < 4; nt++) {
                    float a = cacc[mt][nt][half*2 + 0], b = cacc[mt][nt][half*2 + 1];
                    s += a*a + b*b;
                }
                s += __shfl_xor_sync(0xffffffffu, s, 1);
                s += __shfl_xor_sync(0xffffffffu, s, 2);
                z2[mt][half] = s;
            }
        __syncthreads();
        if (t == 0) {
            #pragma unroll
            for (int mt = 0; mt < 2; mt++)
                #pragma unroll
                for (int half = 0; half < 2; half++) {
                    int r = mt*16 + g + half*8;
                    HBf[r*8 + warpN] = z2[mt][half];
                }
        }
        __syncthreads();
        if (tid < MROW) {
            float ss = 0.f;
            #pragma unroll
            for (int w = 0; w < 8; w++) ss += HBf[tid*8 + w];
            logpx[(size_t)blockIdx.x * MROW + tid] =
                (DGCONST - 0.5f*ss + ldacc) * (1.0f/Dd);
        }
    }

    // ===================== head GEMM: h = z @ Wh1 (3-term) + bh1 =====================
    {
        INIT_ACC_G(bh1);
        #pragma unroll
        for (int c = 0; c < 8; c++) {
            if (c < 7) {
                PIPE_STAGE(g_whi + (c+1)*16384);
            } else {
                CP_WAIT0; __syncthreads();
            }
            PASS_3T(c, BWu + cb); cb ^= 32768u;
        }
        __syncthreads();

        float* stg = (float*)smem;     // [32][264] fp32 overlay
        #pragma unroll
        for (int mt = 0; mt < 2; mt++)
            #pragma unroll
            for (int half = 0; half < 2; half++) {
                int rl = mt*16 + g + half*8;
                int r  = blockIdx.x * MROW + rl;
                #pragma unroll
                for (int nt = 0; nt < 4; nt++) {
                    int c = c_base + nt*8;
                    float* cf = cacc[mt][nt];
                    float v0 = cf[half*2 + 0];
                    float v1 = cf[half*2 + 1];
                    *(float2*)(hout + (size_t)r*Dd + c) = make_float2(v0, v1);
                    stg[(size_t)rl*264 + c]     = v0;
                    stg[(size_t)rl*264 + c + 1] = v1;
                }
            }
        __syncthreads();
        if (tid < Dd) {
            float s = 0.f, q = 0.f;
            #pragma unroll 4
            for (int r = 0; r < MROW; r++) {
                float v = stg[(size_t)r*264 + tid];
                s += v; q += v * v;
            }
            g_part[(size_t)blockIdx.x*2*Dd + tid]      = s;
            g_part[(size_t)blockIdx.x*2*Dd + Dd + tid] = q;
        }
    }
}

// ---------------- BN stats fold (two-stage parallel reduction) ----------------
__global__ void __launch_bounds__(512) stats1_kernel() {
    int b = blockIdx.x, c = threadIdx.x;
    float s = 0.f;
    int i0 = b * (NBLK/64);
    #pragma unroll 4
    for (int i = 0; i < NBLK/64; i++)
        s += g_part[(size_t)(i0 + i)*2*Dd + c];
    g_part2[b*2*Dd + c] = s;
}
__global__ void stats2_kernel(const float* __restrict__ gamma, const float* __restrict__ beta) {
    int c = threadIdx.x;
    float s = 0.f, q = 0.f;
    #pragma unroll
    for (int i = 0; i < 64; i++) {
        s += g_part2[i*2*Dd + c];
        q += g_part2[i*2*Dd + Dd + c];
    }
    float mu  = s * (1.f/Bsz);
    float var = q * (1.f/Bsz) - mu*mu;
    float a = gamma[c] * rsqrtf(var + BN_EPS);
    g_stats[c]      = a;
    g_stats[Dd + c] = beta[c] - mu * a;
}

// ---------------- logits ----------------
__global__ void __launch_bounds__(256) logits_kernel(
    const float* __restrict__ h, const float* __restrict__ Wh2,
    const float* __restrict__ bh2, float* __restrict__ out)
{
    __shared__ float w2s[Dd*NCc];
    __shared__ float As[Dd], Bs[Dd];
    int tid = threadIdx.x;
    for (int i = tid; i < Dd*NCc; i += 256) w2s[i] = Wh2[i];
    if (tid < Dd) { As[tid] = g_stats[tid]; Bs[tid] = g_stats[Dd + tid]; }
    __syncthreads();

    int warp = tid >> 5, lane = tid & 31;
    size_t row = (size_t)blockIdx.x * 8 + warp;
    const float4* hr = (const float4*)(h + row*Dd);
    float4 v0 = hr[lane*2], v1 = hr[lane*2 + 1];
    int k0 = lane * 8;
    float hn[8];
    hn[0] = fmaxf(v0.x*As[k0+0] + Bs[k0+0], 0.f);
    hn[1] = fmaxf(v0.y*As[k0+1] + Bs[k0+1], 0.f);
    hn[2] = fmaxf(v0.z*As[k0+2] + Bs[k0+2], 0.f);
    hn[3] = fmaxf(v0.w*As[k0+3] + Bs[k0+3], 0.f);
    hn[4] = fmaxf(v1.x*As[k0+4] + Bs[k0+4], 0.f);
    hn[5] = fmaxf(v1.y*As[k0+5] + Bs[k0+5], 0.f);
    hn[6] = fmaxf(v1.z*As[k0+6] + Bs[k0+6], 0.f);
    hn[7] = fmaxf(v1.w*As[k0+7] + Bs[k0+7], 0.f);

    float acc[NCc];
    #pragma unroll
    for (int c = 0; c < NCc; c++) acc[c] = 0.f;
    #pragma unroll
    for (int kk = 0; kk < 8; kk++) {
        float x = hn[kk];
        const float* wr = &w2s[(k0+kk)*NCc];
        #pragma unroll
        for (int c = 0; c < NCc; c++) acc[c] += x * wr[c];
    }
    #pragma unroll
    for (int c = 0; c < NCc; c++) {
        #pragma unroll
        for (int o = 16; o; o >>= 1) acc[c] += __shfl_down_sync(0xffffffffu, acc[c], o);
    }
    if (lane == 0) {
        #pragma unroll
        for (int c = 0; c < NCc; c++) out[row*NCc + c] = acc[c] + __ldg(bh2 + c);
    }
}

// ---------------- launch ----------------
extern "C" void kernel_launch(void* const* d_in, const int* in_sizes, int n_in,
                              void* d_out, int out_size)
{
    const float* feat  = (const float*)d_in[0];
    const float* W1    = (const float*)d_in[1];
    const float* b1    = (const float*)d_in[2];
    const float* W2    = (const float*)d_in[3];
    const float* b2    = (const float*)d_in[4];
    const float* gs    = (const float*)d_in[5];
    const float* go    = (const float*)d_in[6];
    const float* P     = (const float*)d_in[7];
    const float* Wh1   = (const float*)d_in[8];
    const float* bh1   = (const float*)d_in[9];
    const float* gamma = (const float*)d_in[10];
    const float* beta  = (const float*)d_in[11];
    const float* Wh2   = (const float*)d_in[12];
    const float* bh2   = (const float*)d_in[13];
    float* out = (float*)d_out;

    cudaFuncSetAttribute(flow_fused, cudaFuncAttributeMaxDynamicSharedMemorySize, SMEMSZ);

    float* bufA = nullptr;
    cudaGetSymbolAddress((void**)&bufA, g_bufA);

    prep_scale<<<Lc, 256>>>(gs);
    prep_wimg<<<(W1T_CNT + W2T_CNT + WHT_CNT + 255)/256, 256>>>(W1, W2, Wh1);
    prep_pimg<<<(PT_CNT + Lc*256 + 255)/256, 256>>>(P, go);

    flow_fused<<<NBLK, NTHR, SMEMSZ>>>(feat, bufA, b1, b2, bh1, out);

    stats1_kernel<<<64, 512>>>();
    stats2_kernel<<<1, 256>>>(gamma, beta);
    logits_kernel<<<Bsz/8, 256>>>(bufA, Wh2, bh2, out + Bsz);
}